// round 1
// baseline (speedup 1.0000x reference)
#include <cuda_runtime.h>

#define BB 8
#define NN 512
#define DD 64
#define HH 64

// Scratch: hq (includes +b1) and hk, [B,N,H] fp32 each (1 MB each).
__device__ float g_hq[BB * NN * HH];
__device__ float g_hk[BB * NN * HH];

// ---------------------------------------------------------------------------
// Kernel 1: precompute hq[b,n,h] = x[b,n,:].(Wq+Wd)[h,:] + b1[h]
//           and       hk[b,n,h] = x[b,n,:].(Wk-Wd)[h,:]
// W1 is [H, 4D] = [64, 256]; blocks of 64, W rows held in registers,
// two passes (q-combo then k-combo) to cap register pressure.
// Grid: 256 blocks, each handles (b, n0..n0+15). 64 threads, thread = h.
// ---------------------------------------------------------------------------
__global__ __launch_bounds__(64) void precompute_hqhk(
    const float* __restrict__ X,
    const float* __restrict__ W1,
    const float* __restrict__ b1)
{
    __shared__ float sx[16 * DD];
    const int t  = threadIdx.x;        // = h
    const int b  = blockIdx.x >> 5;
    const int n0 = (blockIdx.x & 31) * 16;

    // stage the 16 x-rows
    for (int i = t; i < 16 * DD / 4; i += 64) {
        reinterpret_cast<float4*>(sx)[i] =
            reinterpret_cast<const float4*>(X + (b * NN + n0) * DD)[i];
    }
    __syncthreads();

    const int h = t;
    const float bb = __ldg(&b1[h]);
    const float4* w1row = reinterpret_cast<const float4*>(W1 + h * 256);

    // ---- pass A: hq with (Wq + Wd) ----
    {
        float4 w[16];
        #pragma unroll
        for (int j = 0; j < 16; j++) {
            float4 wq = __ldg(&w1row[j]);        // Wq block  [0:64)
            float4 wd = __ldg(&w1row[32 + j]);   // Wd block  [128:192)
            w[j] = make_float4(wq.x + wd.x, wq.y + wd.y, wq.z + wd.z, wq.w + wd.w);
        }
        for (int nn = 0; nn < 16; nn++) {
            const float4* xr = reinterpret_cast<const float4*>(sx + nn * DD);
            float s = 0.f;
            #pragma unroll
            for (int j = 0; j < 16; j++) {
                float4 xv = xr[j];
                s += w[j].x * xv.x + w[j].y * xv.y + w[j].z * xv.z + w[j].w * xv.w;
            }
            g_hq[(b * NN + n0 + nn) * HH + h] = s + bb;
        }
    }
    // ---- pass B: hk with (Wk - Wd) ----
    {
        float4 w[16];
        #pragma unroll
        for (int j = 0; j < 16; j++) {
            float4 wk = __ldg(&w1row[16 + j]);   // Wk block  [64:128)
            float4 wd = __ldg(&w1row[32 + j]);   // Wd block  [128:192)
            w[j] = make_float4(wk.x - wd.x, wk.y - wd.y, wk.z - wd.z, wk.w - wd.w);
        }
        for (int nn = 0; nn < 16; nn++) {
            const float4* xr = reinterpret_cast<const float4*>(sx + nn * DD);
            float s = 0.f;
            #pragma unroll
            for (int j = 0; j < 16; j++) {
                float4 xv = xr[j];
                s += w[j].x * xv.x + w[j].y * xv.y + w[j].z * xv.z + w[j].w * xv.w;
            }
            g_hk[(b * NN + n0 + nn) * HH + h] = s;
        }
    }
}

// ---------------------------------------------------------------------------
// Kernel 2: main DIN pairwise kernel.
// One CTA per (b, q), 64 threads, thread = h.
//   A[d] = Wm[h,d] * x_q[d] held in registers (16 float4).
//   Keys chunked by 64: stage x-tile + hk-tile in smem, score per (k,h) via
//   64 FFMA + PReLU + W2, warp shfl-reduce, smem combine; fused epilogue
//   accumulates encoded[q,d] += score_k * x_k[d] (thread t owns d = t).
// Blocks launched longest-q-first to reduce tail imbalance.
// ---------------------------------------------------------------------------
__global__ __launch_bounds__(64) void din_main(
    const float* __restrict__ X,
    const float* __restrict__ VM,
    const float* __restrict__ W1,
    const float* __restrict__ prelu_a,
    const float* __restrict__ W2,
    const float* __restrict__ b2,
    float* __restrict__ OUT)
{
    __shared__ float sm_x [64 * DD];   // x-tile  [kk][d]
    __shared__ float sm_hk[64 * HH];   // hk-tile [kk][h]
    __shared__ float sm_xq[DD];
    __shared__ float sm_sc[2 * 64];    // per-warp partial scores
    __shared__ float sm_vm[64];        // causal * valid mask per kk

    const int t = threadIdx.x;          // = h, also = output d
    const int b = blockIdx.x & 7;
    const int q = NN - 1 - (blockIdx.x >> 3);   // long rows first
    const int h = t;

    // stage x_q
    sm_xq[t] = X[(b * NN + q) * DD + t];
    __syncthreads();

    // A[d] = Wm[h,d] * x_q[d]  (Wm = W1 block [192:256))
    float4 A[16];
    {
        const float4* wm = reinterpret_cast<const float4*>(W1 + h * 256 + 192);
        const float4* xq = reinterpret_cast<const float4*>(sm_xq);
        #pragma unroll
        for (int j = 0; j < 16; j++) {
            float4 w = __ldg(&wm[j]);
            float4 xv = xq[j];
            A[j] = make_float4(w.x * xv.x, w.y * xv.y, w.z * xv.z, w.w * xv.w);
        }
    }

    const float base  = g_hq[(b * NN + q) * HH + h];   // hq + b1
    const float w2h   = __ldg(&W2[h]);
    const float aslope = __ldg(prelu_a);
    const float b2v   = __ldg(b2);

    float acc = 0.f;   // encoded[b,q,t]

    const int nchunks = (q >> 6) + 1;
    for (int c = 0; c < nchunks; c++) {
        const int k0 = c * 64;
        // ---- stage chunk ----
        {
            const float4* xsrc  = reinterpret_cast<const float4*>(X    + (b * NN + k0) * DD);
            const float4* hksrc = reinterpret_cast<const float4*>(g_hk + (b * NN + k0) * HH);
            float4* xd  = reinterpret_cast<float4*>(sm_x);
            float4* hkd = reinterpret_cast<float4*>(sm_hk);
            for (int i = t; i < 64 * DD / 4; i += 64) {
                xd[i]  = xsrc[i];
                hkd[i] = hksrc[i];
            }
            const int k = k0 + t;
            sm_vm[t] = (k <= q) ? VM[b * NN + k] : 0.f;
        }
        __syncthreads();

        // ---- scores for 64 keys ----
        #pragma unroll 2
        for (int kk = 0; kk < 64; kk++) {
            float s = base + sm_hk[kk * HH + h];
            const float4* xk = reinterpret_cast<const float4*>(sm_x + kk * DD);
            #pragma unroll
            for (int j = 0; j < 16; j++) {
                float4 xv = xk[j];
                s += A[j].x * xv.x + A[j].y * xv.y + A[j].z * xv.z + A[j].w * xv.w;
            }
            float r = (s > 0.f) ? s : aslope * s;       // PReLU
            float p = w2h * r;
            p += __shfl_xor_sync(0xffffffffu, p, 16);
            p += __shfl_xor_sync(0xffffffffu, p, 8);
            p += __shfl_xor_sync(0xffffffffu, p, 4);
            p += __shfl_xor_sync(0xffffffffu, p, 2);
            p += __shfl_xor_sync(0xffffffffu, p, 1);
            if ((t & 31) == 0) sm_sc[(t >> 5) * 64 + kk] = p;
        }
        __syncthreads();

        // ---- fused epilogue: acc += score_k * x_k[t] ----
        #pragma unroll 8
        for (int kk = 0; kk < 64; kk++) {
            float sc = (sm_sc[kk] + sm_sc[64 + kk] + b2v) * sm_vm[kk];
            acc += sc * sm_x[kk * DD + t];
        }
        __syncthreads();
    }

    OUT[(b * NN + q) * DD + t] = acc;
}

// ---------------------------------------------------------------------------
// Launch. Inputs (metadata order):
//  0 past_lengths (int32, unused by reference)
//  1 user_embeddings [8,512,64] f32
//  2 valid_mask [8,512] f32
//  3 W1 [64,256] f32
//  4 b1 [64] f32
//  5 prelu_a [1] f32
//  6 W2 [1,64] f32
//  7 b2 [1] f32
// Output: encoded [8,512,64] f32
// ---------------------------------------------------------------------------
extern "C" void kernel_launch(void* const* d_in, const int* in_sizes, int n_in,
                              void* d_out, int out_size)
{
    const float* X   = (const float*)d_in[1];
    const float* VM  = (const float*)d_in[2];
    const float* W1  = (const float*)d_in[3];
    const float* b1  = (const float*)d_in[4];
    const float* pa  = (const float*)d_in[5];
    const float* W2  = (const float*)d_in[6];
    const float* b2  = (const float*)d_in[7];
    float* OUT = (float*)d_out;

    precompute_hqhk<<<256, 64>>>(X, W1, b1);
    din_main<<<BB * NN, 64>>>(X, VM, W1, pa, W2, b2, OUT);
}

// round 2
// speedup vs baseline: 1.3353x; 1.3353x over previous
#include <cuda_runtime.h>

#define BB 8
#define NN 512
#define DD 64
#define HH 64

typedef unsigned long long ull;

// Scratch: hq (includes +b1) and hk, [B,N,H] fp32 each (1 MB each).
__device__ float g_hq[BB * NN * HH];
__device__ float g_hk[BB * NN * HH];

// ---------------- packed f32x2 helpers (sm_103a) ----------------
static __device__ __forceinline__ ull ffma2(ull a, ull b, ull c) {
    ull d;
    asm("fma.rn.f32x2 %0, %1, %2, %3;" : "=l"(d) : "l"(a), "l"(b), "l"(c));
    return d;
}
static __device__ __forceinline__ ull fadd2(ull a, ull b) {
    ull d;
    asm("add.rn.f32x2 %0, %1, %2;" : "=l"(d) : "l"(a), "l"(b));
    return d;
}
static __device__ __forceinline__ ull pack2(float lo, float hi) {
    ull d;
    asm("mov.b64 %0, {%1, %2};" : "=l"(d) : "f"(lo), "f"(hi));
    return d;
}
static __device__ __forceinline__ void unpack2(ull v, float& lo, float& hi) {
    asm("mov.b64 {%0, %1}, %2;" : "=f"(lo), "=f"(hi) : "l"(v));
}

// ---------------------------------------------------------------------------
// Kernel 1: precompute hq[b,n,h] = x.(Wq+Wd)[h,:] + b1[h],  hk = x.(Wk-Wd)[h,:]
// ---------------------------------------------------------------------------
__global__ __launch_bounds__(64) void precompute_hqhk(
    const float* __restrict__ X,
    const float* __restrict__ W1,
    const float* __restrict__ b1)
{
    __shared__ float sx[16 * DD];
    const int t  = threadIdx.x;        // = h
    const int b  = blockIdx.x >> 5;
    const int n0 = (blockIdx.x & 31) * 16;

    for (int i = t; i < 16 * DD / 4; i += 64) {
        reinterpret_cast<float4*>(sx)[i] =
            reinterpret_cast<const float4*>(X + (b * NN + n0) * DD)[i];
    }
    __syncthreads();

    const int h = t;
    const float bb = __ldg(&b1[h]);
    const float4* w1row = reinterpret_cast<const float4*>(W1 + h * 256);

    {   // hq with (Wq + Wd)
        float4 w[16];
        #pragma unroll
        for (int j = 0; j < 16; j++) {
            float4 wq = __ldg(&w1row[j]);
            float4 wd = __ldg(&w1row[32 + j]);
            w[j] = make_float4(wq.x + wd.x, wq.y + wd.y, wq.z + wd.z, wq.w + wd.w);
        }
        for (int nn = 0; nn < 16; nn++) {
            const float4* xr = reinterpret_cast<const float4*>(sx + nn * DD);
            float s = 0.f;
            #pragma unroll
            for (int j = 0; j < 16; j++) {
                float4 xv = xr[j];
                s += w[j].x * xv.x + w[j].y * xv.y + w[j].z * xv.z + w[j].w * xv.w;
            }
            g_hq[(b * NN + n0 + nn) * HH + h] = s + bb;
        }
    }
    {   // hk with (Wk - Wd)
        float4 w[16];
        #pragma unroll
        for (int j = 0; j < 16; j++) {
            float4 wk = __ldg(&w1row[16 + j]);
            float4 wd = __ldg(&w1row[32 + j]);
            w[j] = make_float4(wk.x - wd.x, wk.y - wd.y, wk.z - wd.z, wk.w - wd.w);
        }
        for (int nn = 0; nn < 16; nn++) {
            const float4* xr = reinterpret_cast<const float4*>(sx + nn * DD);
            float s = 0.f;
            #pragma unroll
            for (int j = 0; j < 16; j++) {
                float4 xv = xr[j];
                s += w[j].x * xv.x + w[j].y * xv.y + w[j].z * xv.z + w[j].w * xv.w;
            }
            g_hk[(b * NN + n0 + nn) * HH + h] = s;
        }
    }
}

// ---------------------------------------------------------------------------
// Kernel 2: main DIN pairwise kernel, packed f32x2 version.
// CTA = 128 threads = 4 warps; warp w handles query q = q_base + w.
// Lane owns the h-pair (2*lane, 2*lane+1) and also the d-pair for output.
// x chunk staged in smem PRE-DUPLICATED as (x,x) pairs so it can feed the
// FFMA2 b-operand directly from a broadcast LDS.128 (2 d per load).
// No syncthreads inside the key loop; scores reduced via shfl-bfly and
// consumed immediately by the fused epilogue.
// ---------------------------------------------------------------------------
__global__ __launch_bounds__(128) void din_main(
    const float* __restrict__ X,
    const float* __restrict__ VM,
    const float* __restrict__ W1,
    const float* __restrict__ prelu_a,
    const float* __restrict__ W2,
    const float* __restrict__ b2,
    float* __restrict__ OUT)
{
    __shared__ float4 sm_xdup[64 * 32];   // 64 keys x 64 d duplicated pairs = 32 KB
    __shared__ float  sm_hk [64 * 64];    // 64 keys x 64 h = 16 KB

    const int tid  = threadIdx.x;
    const int w    = tid >> 5;
    const int lane = tid & 31;
    const int b    = blockIdx.x & 7;
    const int g    = blockIdx.x >> 3;            // 0..127
    const int qb   = (NN - 4) - 4 * g;           // long queries first
    const int q    = qb + w;
    const int h0   = 2 * lane;

    // --- per-thread resident A[d] = (Wm[h0,d]*xq[d], Wm[h1,d]*xq[d]) ---
    ull A[64];
    {
        const float4* wm0 = reinterpret_cast<const float4*>(W1 + h0 * 256 + 192);
        const float4* wm1 = reinterpret_cast<const float4*>(W1 + (h0 + 1) * 256 + 192);
        const float4* xq4 = reinterpret_cast<const float4*>(X + (b * NN + q) * DD);
        #pragma unroll
        for (int j = 0; j < 16; j++) {
            float4 w0 = __ldg(&wm0[j]);
            float4 w1 = __ldg(&wm1[j]);
            float4 xv = __ldg(&xq4[j]);
            A[4 * j + 0] = pack2(w0.x * xv.x, w1.x * xv.x);
            A[4 * j + 1] = pack2(w0.y * xv.y, w1.y * xv.y);
            A[4 * j + 2] = pack2(w0.z * xv.z, w1.z * xv.z);
            A[4 * j + 3] = pack2(w0.w * xv.w, w1.w * xv.w);
        }
    }

    ull base2;
    {
        const float2 bq = *reinterpret_cast<const float2*>(g_hq + (b * NN + q) * HH + h0);
        base2 = pack2(bq.x, bq.y);
    }
    const float2 w2v   = __ldg(reinterpret_cast<const float2*>(W2 + h0));
    const float aslope = __ldg(prelu_a);
    const float b2v    = __ldg(b2);

    float acc0 = 0.f, acc1 = 0.f;

    const int nch_max = ((qb + 3) >> 6) + 1;
    for (int c = 0; c < nch_max; c++) {
        const int k0 = c << 6;
        __syncthreads();  // previous chunk fully consumed
        // ---- stage chunk (all 128 threads) ----
        {
            const float2* xsrc = reinterpret_cast<const float2*>(X + (b * NN + k0) * DD);
            for (int i = tid; i < 2048; i += 128) {
                float2 v = __ldg(&xsrc[i]);
                sm_xdup[i] = make_float4(v.x, v.x, v.y, v.y);
            }
            const float4* hsrc = reinterpret_cast<const float4*>(g_hk + (b * NN + k0) * HH);
            float4* hdst = reinterpret_cast<float4*>(sm_hk);
            for (int i = tid; i < 1024; i += 128) hdst[i] = hsrc[i];
        }
        __syncthreads();

        if (k0 > q) continue;                  // this warp has no keys here

        const float vmA = VM[b * NN + k0 + lane];
        const float vmB = VM[b * NN + k0 + 32 + lane];
        const int kmax = min(63, q - k0);      // exact causal bound

        for (int kk = 0; kk <= kmax; kk++) {
            ull s0 = base2;
            ull s1 = reinterpret_cast<const ull*>(sm_hk)[kk * 32 + lane];
            ull s2 = 0ull, s3 = 0ull;
            const ulonglong2* xr =
                reinterpret_cast<const ulonglong2*>(sm_xdup + kk * 32);
            #pragma unroll
            for (int j = 0; j < 32; j += 2) {
                ulonglong2 xa = xr[j];
                ulonglong2 xb = xr[j + 1];
                s0 = ffma2(A[2 * j + 0], xa.x, s0);
                s1 = ffma2(A[2 * j + 1], xa.y, s1);
                s2 = ffma2(A[2 * j + 2], xb.x, s2);
                s3 = ffma2(A[2 * j + 3], xb.y, s3);
            }
            ull sm = fadd2(fadd2(s0, s2), fadd2(s1, s3));
            float slo, shi;
            unpack2(sm, slo, shi);
            float r0 = (slo > 0.f) ? slo : aslope * slo;   // PReLU
            float r1 = (shi > 0.f) ? shi : aslope * shi;
            float p = fmaf(w2v.x, r0, w2v.y * r1);
            p += __shfl_xor_sync(0xffffffffu, p, 16);
            p += __shfl_xor_sync(0xffffffffu, p, 8);
            p += __shfl_xor_sync(0xffffffffu, p, 4);
            p += __shfl_xor_sync(0xffffffffu, p, 2);
            p += __shfl_xor_sync(0xffffffffu, p, 1);
            float vmv = __shfl_sync(0xffffffffu, (kk < 32) ? vmA : vmB, kk & 31);
            float sc = (p + b2v) * vmv;
            // fused epilogue: lane owns d = (2*lane, 2*lane+1)
            float4 xd = sm_xdup[kk * 32 + lane];   // (x_d0, x_d0, x_d1, x_d1)
            acc0 = fmaf(sc, xd.x, acc0);
            acc1 = fmaf(sc, xd.z, acc1);
        }
    }

    *reinterpret_cast<float2*>(OUT + (b * NN + q) * DD + h0) =
        make_float2(acc0, acc1);
}

// ---------------------------------------------------------------------------
// Inputs (metadata order):
//  0 past_lengths (int32, unused)   1 user_embeddings [8,512,64] f32
//  2 valid_mask [8,512] f32         3 W1 [64,256] f32
//  4 b1 [64] f32                    5 prelu_a [1] f32
//  6 W2 [1,64] f32                  7 b2 [1] f32
// Output: encoded [8,512,64] f32
// ---------------------------------------------------------------------------
extern "C" void kernel_launch(void* const* d_in, const int* in_sizes, int n_in,
                              void* d_out, int out_size)
{
    const float* X   = (const float*)d_in[1];
    const float* VM  = (const float*)d_in[2];
    const float* W1  = (const float*)d_in[3];
    const float* b1  = (const float*)d_in[4];
    const float* pa  = (const float*)d_in[5];
    const float* W2  = (const float*)d_in[6];
    const float* b2  = (const float*)d_in[7];
    float* OUT = (float*)d_out;

    precompute_hqhk<<<256, 64>>>(X, W1, b1);
    din_main<<<BB * NN / 4, 128>>>(X, VM, W1, pa, W2, b2, OUT);
}

// round 3
// speedup vs baseline: 2.0998x; 1.5725x over previous
#include <cuda_runtime.h>

#define BB 8
#define NN 512
#define DD 64
#define HH 64

typedef unsigned long long ull;

// Scratch: hq (includes +b1) and hk, [B,N,H] fp32 each (1 MB each).
__device__ float g_hq[BB * NN * HH];
__device__ float g_hk[BB * NN * HH];

// ---------------- packed f32x2 helpers (sm_103a) ----------------
static __device__ __forceinline__ ull ffma2(ull a, ull b, ull c) {
    ull d;
    asm("fma.rn.f32x2 %0, %1, %2, %3;" : "=l"(d) : "l"(a), "l"(b), "l"(c));
    return d;
}
static __device__ __forceinline__ ull pack2(float lo, float hi) {
    ull d;
    asm("mov.b64 %0, {%1, %2};" : "=l"(d) : "f"(lo), "f"(hi));
    return d;
}
static __device__ __forceinline__ void unpack2(ull v, float& lo, float& hi) {
    asm("mov.b64 {%0, %1}, %2;" : "=f"(lo), "=f"(hi) : "l"(v));
}

// ---------------------------------------------------------------------------
// Kernel 1: precompute hq[b,n,h] = x.(Wq+Wd)[h,:] + b1[h],  hk = x.(Wk-Wd)[h,:]
// ---------------------------------------------------------------------------
__global__ __launch_bounds__(64) void precompute_hqhk(
    const float* __restrict__ X,
    const float* __restrict__ W1,
    const float* __restrict__ b1)
{
    __shared__ float sx[16 * DD];
    const int t  = threadIdx.x;        // = h
    const int b  = blockIdx.x >> 5;
    const int n0 = (blockIdx.x & 31) * 16;

    for (int i = t; i < 16 * DD / 4; i += 64) {
        reinterpret_cast<float4*>(sx)[i] =
            reinterpret_cast<const float4*>(X + (b * NN + n0) * DD)[i];
    }
    __syncthreads();

    const int h = t;
    const float bb = __ldg(&b1[h]);
    const float4* w1row = reinterpret_cast<const float4*>(W1 + h * 256);

    {   // hq with (Wq + Wd)
        float4 w[16];
        #pragma unroll
        for (int j = 0; j < 16; j++) {
            float4 wq = __ldg(&w1row[j]);
            float4 wd = __ldg(&w1row[32 + j]);
            w[j] = make_float4(wq.x + wd.x, wq.y + wd.y, wq.z + wd.z, wq.w + wd.w);
        }
        for (int nn = 0; nn < 16; nn++) {
            const float4* xr = reinterpret_cast<const float4*>(sx + nn * DD);
            float s = 0.f;
            #pragma unroll
            for (int j = 0; j < 16; j++) {
                float4 xv = xr[j];
                s += w[j].x * xv.x + w[j].y * xv.y + w[j].z * xv.z + w[j].w * xv.w;
            }
            g_hq[(b * NN + n0 + nn) * HH + h] = s + bb;
        }
    }
    {   // hk with (Wk - Wd)
        float4 w[16];
        #pragma unroll
        for (int j = 0; j < 16; j++) {
            float4 wk = __ldg(&w1row[16 + j]);
            float4 wd = __ldg(&w1row[32 + j]);
            w[j] = make_float4(wk.x - wd.x, wk.y - wd.y, wk.z - wd.z, wk.w - wd.w);
        }
        for (int nn = 0; nn < 16; nn++) {
            const float4* xr = reinterpret_cast<const float4*>(sx + nn * DD);
            float s = 0.f;
            #pragma unroll
            for (int j = 0; j < 16; j++) {
                float4 xv = xr[j];
                s += w[j].x * xv.x + w[j].y * xv.y + w[j].z * xv.z + w[j].w * xv.w;
            }
            g_hk[(b * NN + n0 + nn) * HH + h] = s;
        }
    }
}

// ---------------------------------------------------------------------------
// Kernel 2: main DIN kernel, d-packed f32x2 + batched butterfly reduction.
// CTA = 128 threads = 4 warps; warp w owns query q = qb + w.
// Lane owns h-pair (2*lane, 2*lane+1); A rows packed over d-pairs so the
// FFMA2 b-operand is a natural float2 straight from the (non-duplicated)
// smem x tile. Keys processed in groups of 16: per-lane partial scores ->
// 31-shfl transpose reduce -> lane (l&15) holds score of key (l&15) ->
// epilogue 1 shfl + 1 LDS.64 + 1 FFMA2 per key.
// ---------------------------------------------------------------------------
__global__ __launch_bounds__(128) void din_main(
    const float* __restrict__ X,
    const float* __restrict__ VM,
    const float* __restrict__ W1,
    const float* __restrict__ prelu_a,
    const float* __restrict__ W2,
    const float* __restrict__ b2,
    float* __restrict__ OUT)
{
    __shared__ float sm_x [64 * DD];   // 16 KB
    __shared__ float sm_hk[64 * HH];   // 16 KB

    const int tid  = threadIdx.x;
    const int w    = tid >> 5;
    const int lane = tid & 31;
    const int b    = blockIdx.x & 7;
    const int g    = blockIdx.x >> 3;            // 0..127
    const int qb   = (NN - 4) - 4 * g;           // long queries first
    const int q    = qb + w;
    const int h0   = 2 * lane;

    // --- A0/A1: Wm row (h0 / h0+1) * xq, packed over d-pairs (32 ull each) ---
    ull A0[32], A1[32];
    {
        const float4* wm0 = reinterpret_cast<const float4*>(W1 + h0 * 256 + 192);
        const float4* wm1 = reinterpret_cast<const float4*>(W1 + (h0 + 1) * 256 + 192);
        const float4* xq4 = reinterpret_cast<const float4*>(X + (b * NN + q) * DD);
        #pragma unroll
        for (int j = 0; j < 16; j++) {
            float4 w0 = __ldg(&wm0[j]);
            float4 w1 = __ldg(&wm1[j]);
            float4 xv = __ldg(&xq4[j]);
            A0[2 * j]     = pack2(w0.x * xv.x, w0.y * xv.y);
            A0[2 * j + 1] = pack2(w0.z * xv.z, w0.w * xv.w);
            A1[2 * j]     = pack2(w1.x * xv.x, w1.y * xv.y);
            A1[2 * j + 1] = pack2(w1.z * xv.z, w1.w * xv.w);
        }
    }

    const float2 bq    = *reinterpret_cast<const float2*>(g_hq + (b * NN + q) * HH + h0);
    const float2 w2v   = __ldg(reinterpret_cast<const float2*>(W2 + h0));
    const float aslope = __ldg(prelu_a);
    const float b2v    = __ldg(b2);

    ull accp = 0ull;                  // packed output acc for d = (2*lane, 2*lane+1)

    const int nch = ((qb + 3) >> 6) + 1;
    for (int c = 0; c < nch; c++) {
        const int k0 = c << 6;
        __syncthreads();              // previous chunk fully consumed
        {   // ---- stage 64-key chunk: x (16KB) + hk (16KB) ----
            const float4* xsrc = reinterpret_cast<const float4*>(X    + (b * NN + k0) * DD);
            const float4* hsrc = reinterpret_cast<const float4*>(g_hk + (b * NN + k0) * HH);
            float4* xd = reinterpret_cast<float4*>(sm_x);
            float4* hd = reinterpret_cast<float4*>(sm_hk);
            #pragma unroll
            for (int i = 0; i < 8; i++) {
                xd[tid + 128 * i] = __ldg(&xsrc[tid + 128 * i]);
                hd[tid + 128 * i] = __ldg(&hsrc[tid + 128 * i]);
            }
        }
        __syncthreads();

        #pragma unroll 1
        for (int grp = 0; grp < 4; grp++) {
            const int gk = grp << 4;                 // group base within chunk
            if (k0 + gk > q) break;                  // warp-uniform

            // ---- per-lane partial scores for 16 keys ----
            float p[16];
            #pragma unroll
            for (int kk = 0; kk < 16; kk++) {
                const int kp = gk + kk;
                const ulonglong2* xr =
                    reinterpret_cast<const ulonglong2*>(sm_x + kp * DD);
                ull a0 = 0ull, a1 = 0ull, c0 = 0ull, c1 = 0ull;
                #pragma unroll
                for (int j = 0; j < 16; j++) {
                    ulonglong2 xv = xr[j];
                    a0 = ffma2(A0[2 * j],     xv.x, a0);
                    a1 = ffma2(A0[2 * j + 1], xv.y, a1);
                    c0 = ffma2(A1[2 * j],     xv.x, c0);
                    c1 = ffma2(A1[2 * j + 1], xv.y, c1);
                }
                float hk0, hk1;
                unpack2(reinterpret_cast<const ull*>(sm_hk)[kp * 32 + lane], hk0, hk1);
                float alo, ahi, clo, chi;
                unpack2(a0, alo, ahi);  float sa = alo + ahi;
                unpack2(a1, alo, ahi);  sa += alo + ahi;
                unpack2(c0, clo, chi);  float sc2 = clo + chi;
                unpack2(c1, clo, chi);  sc2 += clo + chi;
                float s0 = sa  + hk0 + bq.x;
                float s1 = sc2 + hk1 + bq.y;
                float r0 = fmaxf(s0, 0.f) + aslope * fminf(s0, 0.f);   // PReLU
                float r1 = fmaxf(s1, 0.f) + aslope * fminf(s1, 0.f);
                p[kk] = fmaf(w2v.x, r0, w2v.y * r1);
            }

            // ---- transpose-reduce 16 values over 32 lanes (31 shfls) ----
            #pragma unroll
            for (int i = 0; i < 16; i++)
                p[i] += __shfl_xor_sync(0xffffffffu, p[i], 16);
            #pragma unroll
            for (int i = 0; i < 8; i++) {
                bool hi = (lane & 8) != 0;
                float send = hi ? p[i] : p[i + 8];
                float keep = hi ? p[i + 8] : p[i];
                p[i] = keep + __shfl_xor_sync(0xffffffffu, send, 8);
            }
            #pragma unroll
            for (int i = 0; i < 4; i++) {
                bool hi = (lane & 4) != 0;
                float send = hi ? p[i] : p[i + 4];
                float keep = hi ? p[i + 4] : p[i];
                p[i] = keep + __shfl_xor_sync(0xffffffffu, send, 4);
            }
            #pragma unroll
            for (int i = 0; i < 2; i++) {
                bool hi = (lane & 2) != 0;
                float send = hi ? p[i] : p[i + 2];
                float keep = hi ? p[i + 2] : p[i];
                p[i] = keep + __shfl_xor_sync(0xffffffffu, send, 2);
            }
            {
                bool hi = (lane & 1) != 0;
                float send = hi ? p[0] : p[1];
                float keep = hi ? p[1] : p[0];
                p[0] = keep + __shfl_xor_sync(0xffffffffu, send, 1);
            }
            // lane l now holds total for key (l & 15) of this group.

            const int klane = k0 + gk + (lane & 15);
            const float cm  = (klane <= q) ? VM[b * NN + klane] : 0.f;
            const float sc  = (p[0] + b2v) * cm;

            // ---- fused epilogue ----
            #pragma unroll
            for (int kk = 0; kk < 16; kk++) {
                float scb = __shfl_sync(0xffffffffu, sc, kk);
                ull x2 = reinterpret_cast<const ull*>(sm_x + (gk + kk) * DD)[lane];
                accp = ffma2(pack2(scb, scb), x2, accp);
            }
        }
    }

    float o0, o1;
    unpack2(accp, o0, o1);
    *reinterpret_cast<float2*>(OUT + (b * NN + q) * DD + h0) = make_float2(o0, o1);
}

// ---------------------------------------------------------------------------
// Inputs (metadata order):
//  0 past_lengths (int32, unused)   1 user_embeddings [8,512,64] f32
//  2 valid_mask [8,512] f32         3 W1 [64,256] f32
//  4 b1 [64] f32                    5 prelu_a [1] f32
//  6 W2 [1,64] f32                  7 b2 [1] f32
// Output: encoded [8,512,64] f32
// ---------------------------------------------------------------------------
extern "C" void kernel_launch(void* const* d_in, const int* in_sizes, int n_in,
                              void* d_out, int out_size)
{
    const float* X   = (const float*)d_in[1];
    const float* VM  = (const float*)d_in[2];
    const float* W1  = (const float*)d_in[3];
    const float* b1  = (const float*)d_in[4];
    const float* pa  = (const float*)d_in[5];
    const float* W2  = (const float*)d_in[6];
    const float* b2  = (const float*)d_in[7];
    float* OUT = (float*)d_out;

    precompute_hqhk<<<256, 64>>>(X, W1, b1);
    din_main<<<BB * NN / 4, 128>>>(X, VM, W1, pa, W2, b2, OUT);
}